// round 13
// baseline (speedup 1.0000x reference)
#include <cuda_runtime.h>
#include <cuda_fp16.h>
#include <math.h>
#include <stdint.h>

#define Dv   128
#define Bv   4096

// SMEM word layout (main kernel)
#define S_OFF     0                       // fp32 stage: 128x128 (cp.async target)
#define AH0_OFF   16384                   // fp16 A tile 0: 128 x 136 halves (272B pitch)
#define AH_STRIDE 8704                    // words per AH buffer (34816 B)
#define AH1_OFF   (AH0_OFF + AH_STRIDE)   // 25088
#define WH_OFF    (AH1_OFF + AH_STRIDE)   // 33792
#define W2_OFF    (WH_OFF + AH_STRIDE)    // 42496
#define RED_OFF   (W2_OFF + 128)          // 42624
#define SMEM_WORDS (RED_OFF + 256)        // 42880 -> 171520 B

// Scratch globals
__device__ float g_base[Bv * Dv];                 // per-graph base rows (2 MB)
__device__ __align__(16) __half g_Wh[128 * 136];  // W1a^T fp16, pitch 136 halves
__device__ int   g_is64;

// ---------------- helpers ----------------
__device__ __forceinline__ uint32_t smem_u32(const void* p) {
    uint32_t a;
    asm("{ .reg .u64 t; cvta.to.shared.u64 t, %1; cvt.u32.u64 %0, t; }" : "=r"(a) : "l"(p));
    return a;
}
__device__ __forceinline__ uint32_t pack_h2(float lo, float hi) {
    uint32_t r;
    asm("cvt.rn.f16x2.f32 %0, %1, %2;" : "=r"(r) : "f"(hi), "f"(lo));
    return r;
}
#define CP_ASYNC16(dst, src) \
    asm volatile("cp.async.cg.shared.global [%0], [%1], 16;" :: "r"(dst), "l"(src) : "memory")
#define CP_COMMIT() asm volatile("cp.async.commit_group;" ::: "memory")
#define CP_WAIT0()  asm volatile("cp.async.wait_group 0;" ::: "memory")

#define LDSM_X4(r0, r1, r2, r3, addr)                                          \
    asm volatile("ldmatrix.sync.aligned.m8n8.x4.shared.b16 {%0,%1,%2,%3}, [%4];" \
        : "=r"(r0), "=r"(r1), "=r"(r2), "=r"(r3) : "r"(addr))

// mma.sync m16n8k16 fp16 -> fp32 accum
#define MMA_F16(c, a, b0_, b1_)                                                \
    asm volatile(                                                              \
        "mma.sync.aligned.m16n8k16.row.col.f32.f16.f16.f32 "                   \
        "{%0,%1,%2,%3}, {%4,%5,%6,%7}, {%8,%9}, {%0,%1,%2,%3};"                \
        : "+f"((c)[0]), "+f"((c)[1]), "+f"((c)[2]), "+f"((c)[3])               \
        : "r"((a)[0]), "r"((a)[1]), "r"((a)[2]), "r"((a)[3]),                  \
          "r"(b0_), "r"(b1_))

// gelu(x) = 0.5x(1+tanh(0.79788456x + 0.03567741x^3)) -- single MUFU tanh
__device__ __forceinline__ float gelu_fast(float x) {
    const float z = x * fmaf(0.035677408f, x * x, 0.7978845608f);
    float t;
    asm("tanh.approx.f32 %0, %1;" : "=f"(t) : "f"(z));
    const float hx = 0.5f * x;
    return fmaf(hx, t, hx);
}

// ---------------------------------------------------------------------------
// aux: blocks 0..63 build g_Wh = fp16(W1a^T) at pitch 136;
//      block 64 detects batch dtype (word [C-1] is 0 iff int64).
// ---------------------------------------------------------------------------
__global__ void __launch_bounds__(256) aux_kernel(const float* __restrict__ W1,
                                                  const int* __restrict__ batch_words,
                                                  int C) {
    if (blockIdx.x == 64) {
        if (threadIdx.x == 0) g_is64 = (batch_words[C - 1] == 0) ? 1 : 0;
        return;
    }
    const int idx = blockIdx.x * 256 + threadIdx.x;   // 16384
    const int n = idx >> 7, k = idx & 127;
    g_Wh[n * 136 + k] = __float2half_rn(W1[k * Dv + n]);
}

// base[b][d] = b1[d] + z_local[b]·W1[128:256] + z_meta·W1[256:384]
__global__ void __launch_bounds__(128) prep_kernel(
    const float* __restrict__ z_local, const float* __restrict__ z_meta,
    const float* __restrict__ W1, const float* __restrict__ b1)
{
    extern __shared__ float smem_f[];
    float* Wp  = smem_f;
    float* zsh = smem_f + 256 * Dv;
    const int tid = threadIdx.x;

    const float4* Wsrc = (const float4*)(W1 + Dv * Dv);
    float4* Wdst = (float4*)Wp;
    for (int i = tid; i < 256 * Dv / 4; i += 128) Wdst[i] = Wsrc[i];
    zsh[Dv + tid] = z_meta[tid];
    __syncthreads();

    const int b0 = blockIdx.x * 32;
    for (int g = 0; g < 32; ++g) {
        const int b = b0 + g;
        zsh[tid] = z_local[b * Dv + tid];
        __syncthreads();
        float a0 = 0.f, a1 = 0.f, a2 = 0.f, a3 = 0.f;
        #pragma unroll 4
        for (int k = 0; k < 256; k += 4) {
            a0 = fmaf(zsh[k + 0], Wp[(k + 0) * Dv + tid], a0);
            a1 = fmaf(zsh[k + 1], Wp[(k + 1) * Dv + tid], a1);
            a2 = fmaf(zsh[k + 2], Wp[(k + 2) * Dv + tid], a2);
            a3 = fmaf(zsh[k + 3], Wp[(k + 3) * Dv + tid], a3);
        }
        g_base[b * Dv + tid] = b1[tid] + ((a0 + a1) + (a2 + a3));
        __syncthreads();
    }
}

// ---------------------------------------------------------------------------
// Persistent main kernel, 256 threads (8 warps, warp tile 32M x 64N — spill-
// free at the 255-reg cap), fp16 m16n8k16, fully pipelined: per-ks the
// mainloop of tile i carries the GELU epilogue of tile i-1 (base loads
// register-prefetched 2 ks ahead) and (ks>=4) the fp32->fp16 convert of
// tile i+1 (own cp.async bytes -> per-thread wait, no barrier).
// ---------------------------------------------------------------------------
__global__ void __launch_bounds__(256, 1) main_kernel(
    const float* __restrict__ nodes,
    const float* __restrict__ W2,
    const float* __restrict__ b2,
    const void*  __restrict__ batch,
    float* __restrict__ out, int C, int T)
{
    extern __shared__ float smem_f[];
    const uint32_t smem_base = smem_u32(smem_f);
    float* w2sh = smem_f + W2_OFF;
    float* red  = smem_f + RED_OFF;

    const int tid  = threadIdx.x;
    const int lane = tid & 31;
    const int warp = tid >> 5;
    const int wm   = warp >> 1;          // 0..3: rows wm*32
    const int wn   = warp & 1;           // 0..1: cols wn*64
    const int G    = gridDim.x;

    // ---- one-time Wh stage (34816 B = 2176 float4) ----
    {
        const float4* src = (const float4*)g_Wh;
        float4* dst = (float4*)(smem_f + WH_OFF);
        for (int idx = tid; idx < 2176; idx += 256) dst[idx] = src[idx];
        if (tid < 128) w2sh[tid] = W2[tid];
    }
    const float b2v  = b2[0];
    const int   is64 = g_is64;
    const int*       bt32 = (const int*)batch;
    const long long* bt64 = (const long long*)batch;

    // ---- ldmatrix lane addresses (fp16, pitch 272B) ----
    const int rowA = wm * 32 + (lane & 7) + ((lane >> 3) & 1) * 8;
    const uint32_t aA0 = smem_base + AH0_OFF * 4 + (uint32_t)rowA * 272
                       + ((lane >> 4) & 1) * 16;
    uint32_t bAdr[4];
    #pragma unroll
    for (int p = 0; p < 4; ++p) {
        const int nB = wn * 64 + p * 16 + (lane & 7) + ((lane >> 4) & 1) * 8;
        bAdr[p] = smem_base + WH_OFF * 4 + (uint32_t)nB * 272
                + ((lane >> 3) & 1) * 16;
    }

    auto issueA = [&](int t) {
        const int g0 = t * 128;
        int nr = C - g0; if (nr > 128) nr = 128;
        const char* src0 = (const char*)(nodes + (size_t)g0 * Dv);
        #pragma unroll
        for (int j = 0; j < 16; ++j) {
            const int e = j * 256 + tid;
            const int r = e >> 5, c = e & 31;
            if (r < nr) {
                const uint32_t dst = smem_base + (uint32_t)(r * 128 + c * 4) * 4;
                CP_ASYNC16(dst, src0 + (size_t)r * 512 + c * 16);
            }
        }
    };
    auto cvtChunk = [&](int wp, int j) {
        const int fi = j * 256 + tid;
        const int r = fi >> 5, c4 = fi & 31;
        const float4 v = ((const float4*)smem_f)[fi];
        uint2 hh;
        hh.x = pack_h2(v.x, v.y);
        hh.y = pack_h2(v.z, v.w);
        *(uint2*)((char*)smem_f + (AH0_OFF + wp * AH_STRIDE) * 4 + r * 272 + c4 * 8) = hh;
    };
    auto loadBidx = [&](int gr0, int bidx[2][2]) {
        #pragma unroll
        for (int tm = 0; tm < 2; ++tm)
            #pragma unroll
            for (int rh = 0; rh < 2; ++rh) {
                const int gr = gr0 + wm * 32 + tm * 16 + rh * 8 + (lane >> 2);
                bidx[tm][rh] = (gr < C) ? (is64 ? (int)bt64[gr] : bt32[gr]) : 0;
            }
    };
    auto finishEpi = [&](int pgr0, float pp[4]) {
        #pragma unroll
        for (int tm = 0; tm < 2; ++tm)
            #pragma unroll
            for (int rh = 0; rh < 2; ++rh) {
                float partial = pp[tm * 2 + rh];
                partial += __shfl_xor_sync(0xFFFFFFFFu, partial, 1);
                partial += __shfl_xor_sync(0xFFFFFFFFu, partial, 2);
                const int row = wm * 32 + tm * 16 + rh * 8 + (lane >> 2);
                if ((lane & 3) == 0) red[row * 2 + wn] = partial;
            }
        __syncthreads();
        if (tid < 128) {
            const int g2 = pgr0 + tid;
            if (g2 < C) out[g2] = red[tid * 2] + red[tid * 2 + 1] + b2v;
        }
    };

    float accN[16][4], accO[16][4];   // [tm*8+nt][c]
    int   pbidx[2][2];
    int   pgr0 = 0;
    const int n0base = wn * 64 + (lane & 3) * 2;

    // base-load ring (4 slots, prefetch distance 4 chunks = 2 ks)
    float2 rA0[4], rA1[4];
    auto ldBase = [&](int c, float2& o0, float2& o1) {
        const int tm = c >> 3, nt = c & 7;
        const int n0 = n0base + nt * 8;
        o0 = __ldg((const float2*)(g_base + pbidx[tm][0] * Dv + n0));
        o1 = __ldg((const float2*)(g_base + pbidx[tm][1] * Dv + n0));
    };

    int tile = blockIdx.x;
    if (tile >= T) return;

    // ---- prologue: stage + convert first tile serially; prefetch tile+G ----
    issueA(tile);
    CP_COMMIT();
    CP_WAIT0();
    #pragma unroll
    for (int j = 0; j < 16; ++j) cvtChunk(0, j);
    __syncthreads();
    if (tile + G < T) issueA(tile + G);
    CP_COMMIT();

    int ahp = 0;
    int doEpi = 0;

    for (; tile < T; tile += G) {
        int bidx[2][2];
        loadBidx(tile * 128, bidx);

        #pragma unroll
        for (int n = 0; n < 16; ++n)
            #pragma unroll
            for (int i = 0; i < 4; ++i) accN[n][i] = 0.f;

        float pp[4] = {0.f, 0.f, 0.f, 0.f};
        const uint32_t aA = aA0 + (uint32_t)ahp * (AH_STRIDE * 4);
        const int wp = ahp ^ 1;
        const int cvtNext = (tile + G < T);

        // preload base values for epilogue chunks 0..3
        if (doEpi) {
            #pragma unroll
            for (int c = 0; c < 4; ++c) ldBase(c, rA0[c], rA1[c]);
        }

        #pragma unroll
        for (int ks = 0; ks < 8; ++ks) {
            uint32_t a0[4], a1[4], u[4][4];
            LDSM_X4(a0[0], a0[1], a0[2], a0[3], aA + ks * 32);
            LDSM_X4(a1[0], a1[1], a1[2], a1[3], aA + ks * 32 + 16 * 272);
            #pragma unroll
            for (int q = 0; q < 4; ++q)
                LDSM_X4(u[q][0], u[q][1], u[q][2], u[q][3], bAdr[q] + ks * 32);

            // epilogue chunks 2ks, 2ks+1 of tile i-1 (base prefetched 2 ks ago)
            if (doEpi) {
                #pragma unroll
                for (int cc = 0; cc < 2; ++cc) {
                    const int c = ks * 2 + cc;
                    const int tm = c >> 3, nt = c & 7, sl = c & 3;
                    const int n0 = n0base + nt * 8;
                    const float2 w2v = *(const float2*)(w2sh + n0);
                    const float2 bv0 = rA0[sl], bv1 = rA1[sl];
                    const float x0 = accO[tm * 8 + nt][0] + bv0.x;
                    const float x1 = accO[tm * 8 + nt][1] + bv0.y;
                    const float x2 = accO[tm * 8 + nt][2] + bv1.x;
                    const float x3 = accO[tm * 8 + nt][3] + bv1.y;
                    pp[tm * 2 + 0] = fmaf(gelu_fast(x0), w2v.x, pp[tm * 2 + 0]);
                    pp[tm * 2 + 0] = fmaf(gelu_fast(x1), w2v.y, pp[tm * 2 + 0]);
                    pp[tm * 2 + 1] = fmaf(gelu_fast(x2), w2v.x, pp[tm * 2 + 1]);
                    pp[tm * 2 + 1] = fmaf(gelu_fast(x3), w2v.y, pp[tm * 2 + 1]);
                    if (c + 4 < 16) ldBase(c + 4, rA0[sl], rA1[sl]);
                }
            }

            // convert chunks of tile i+1 (4 per ks, ks>=4)
            if (ks == 4) CP_WAIT0();
            if (ks >= 4 && cvtNext) {
                cvtChunk(wp, (ks - 4) * 4 + 0);
                cvtChunk(wp, (ks - 4) * 4 + 1);
                cvtChunk(wp, (ks - 4) * 4 + 2);
                cvtChunk(wp, (ks - 4) * 4 + 3);
            }

            #pragma unroll
            for (int q = 0; q < 4; ++q) {
                MMA_F16(accN[2 * q + 0], a0, u[q][0], u[q][1]);
                MMA_F16(accN[2 * q + 1], a0, u[q][2], u[q][3]);
                MMA_F16(accN[8 + 2 * q + 0], a1, u[q][0], u[q][1]);
                MMA_F16(accN[8 + 2 * q + 1], a1, u[q][2], u[q][3]);
            }
        }

        // S is consumed; prefetch tile i+2
        if (tile + 2 * G < T) issueA(tile + 2 * G);
        CP_COMMIT();

        if (doEpi) finishEpi(pgr0, pp);
        else       __syncthreads();      // publish AH[wp] for the next body

        #pragma unroll
        for (int n = 0; n < 16; ++n)
            #pragma unroll
            for (int i = 0; i < 4; ++i) accO[n][i] = accN[n][i];
        pbidx[0][0] = bidx[0][0]; pbidx[0][1] = bidx[0][1];
        pbidx[1][0] = bidx[1][0]; pbidx[1][1] = bidx[1][1];
        pgr0 = tile * 128;
        doEpi = 1;
        ahp ^= 1;
    }

    // ---- drain: standalone epilogue for the last tile ----
    {
        float pp[4] = {0.f, 0.f, 0.f, 0.f};
        #pragma unroll
        for (int c = 0; c < 16; ++c) {
            const int tm = c >> 3, nt = c & 7;
            const int n0 = n0base + nt * 8;
            const float2 w2v = *(const float2*)(w2sh + n0);
            const float2 bv0 = __ldg((const float2*)(g_base + pbidx[tm][0] * Dv + n0));
            const float2 bv1 = __ldg((const float2*)(g_base + pbidx[tm][1] * Dv + n0));
            const float x0 = accO[tm * 8 + nt][0] + bv0.x;
            const float x1 = accO[tm * 8 + nt][1] + bv0.y;
            const float x2 = accO[tm * 8 + nt][2] + bv1.x;
            const float x3 = accO[tm * 8 + nt][3] + bv1.y;
            pp[tm * 2 + 0] = fmaf(gelu_fast(x0), w2v.x, pp[tm * 2 + 0]);
            pp[tm * 2 + 0] = fmaf(gelu_fast(x1), w2v.y, pp[tm * 2 + 0]);
            pp[tm * 2 + 1] = fmaf(gelu_fast(x2), w2v.x, pp[tm * 2 + 1]);
            pp[tm * 2 + 1] = fmaf(gelu_fast(x3), w2v.y, pp[tm * 2 + 1]);
        }
        __syncthreads();
        finishEpi(pgr0, pp);
    }
}

// ---------------------------------------------------------------------------
extern "C" void kernel_launch(void* const* d_in, const int* in_sizes, int n_in,
                              void* d_out, int out_size)
{
    const float* nodes   = (const float*)d_in[0];
    const float* z_local = (const float*)d_in[1];
    const float* z_meta  = (const float*)d_in[2];
    const float* W1      = (const float*)d_in[3];
    const float* b1      = (const float*)d_in[4];
    const float* W2      = (const float*)d_in[5];
    const float* b2      = (const float*)d_in[6];
    const void*  batch   = d_in[7];
    float* out = (float*)d_out;

    const int C = in_sizes[7];
    const int B = in_sizes[1] / Dv;
    const int T = (C + 127) / 128;

    int dev = 0, nsm = 148;
    cudaGetDevice(&dev);
    cudaDeviceGetAttribute(&nsm, cudaDevAttrMultiProcessorCount, dev);

    const int PREP_SMEM = (256 * Dv + 256) * (int)sizeof(float);   // 132096
    const int MAIN_SMEM = SMEM_WORDS * (int)sizeof(float);         // 171520

    cudaFuncSetAttribute(prep_kernel, cudaFuncAttributeMaxDynamicSharedMemorySize, PREP_SMEM);
    cudaFuncSetAttribute(main_kernel, cudaFuncAttributeMaxDynamicSharedMemorySize, MAIN_SMEM);

    aux_kernel<<<65, 256>>>(W1, (const int*)batch, C);
    prep_kernel<<<B / 32, 128, PREP_SMEM>>>(z_local, z_meta, W1, b1);

    main_kernel<<<nsm, 256, MAIN_SMEM>>>(nodes, W2, b2, batch, out, C, T);
}

// round 14
// speedup vs baseline: 1.5971x; 1.5971x over previous
#include <cuda_runtime.h>
#include <cuda_fp16.h>
#include <math.h>
#include <stdint.h>

#define Dv   128
#define Bv   4096

// SMEM word layout (main kernel)
#define S_OFF     0                       // fp32 stage: 128x128 (cp.async target)
#define AH0_OFF   16384                   // fp16 A tile 0: 128 x 136 halves (272B pitch)
#define AH_STRIDE 8704                    // words per AH buffer (34816 B)
#define AH1_OFF   (AH0_OFF + AH_STRIDE)   // 25088
#define WH_OFF    (AH1_OFF + AH_STRIDE)   // 33792
#define W2_OFF    (WH_OFF + AH_STRIDE)    // 42496
#define RED_OFF   (W2_OFF + 128)          // 42624
#define SMEM_WORDS (RED_OFF + 512)        // 43136 -> 172544 B

// Scratch globals
__device__ float g_base[Bv * Dv];                 // per-graph base rows (2 MB)
__device__ __align__(16) __half g_Wh[128 * 136];  // W1a^T fp16, pitch 136 halves
__device__ int   g_is64;

// ---------------- helpers ----------------
__device__ __forceinline__ uint32_t smem_u32(const void* p) {
    uint32_t a;
    asm("{ .reg .u64 t; cvta.to.shared.u64 t, %1; cvt.u32.u64 %0, t; }" : "=r"(a) : "l"(p));
    return a;
}
__device__ __forceinline__ uint32_t pack_h2(float lo, float hi) {
    uint32_t r;
    asm("cvt.rn.f16x2.f32 %0, %1, %2;" : "=r"(r) : "f"(hi), "f"(lo));
    return r;
}
#define CP_ASYNC16(dst, src) \
    asm volatile("cp.async.cg.shared.global [%0], [%1], 16;" :: "r"(dst), "l"(src) : "memory")
#define CP_COMMIT() asm volatile("cp.async.commit_group;" ::: "memory")
#define CP_WAIT0()  asm volatile("cp.async.wait_group 0;" ::: "memory")

#define LDSM_X4(r0, r1, r2, r3, addr)                                          \
    asm volatile("ldmatrix.sync.aligned.m8n8.x4.shared.b16 {%0,%1,%2,%3}, [%4];" \
        : "=r"(r0), "=r"(r1), "=r"(r2), "=r"(r3) : "r"(addr))

// mma.sync m16n8k16 fp16 -> fp32 accum
#define MMA_F16(c, a, b0_, b1_)                                                \
    asm volatile(                                                              \
        "mma.sync.aligned.m16n8k16.row.col.f32.f16.f16.f32 "                   \
        "{%0,%1,%2,%3}, {%4,%5,%6,%7}, {%8,%9}, {%0,%1,%2,%3};"                \
        : "+f"((c)[0]), "+f"((c)[1]), "+f"((c)[2]), "+f"((c)[3])               \
        : "r"((a)[0]), "r"((a)[1]), "r"((a)[2]), "r"((a)[3]),                  \
          "r"(b0_), "r"(b1_))

// gelu(x) = 0.5x(1+tanh(0.79788456x + 0.03567741x^3)) -- single MUFU tanh
__device__ __forceinline__ float gelu_fast(float x) {
    const float z = x * fmaf(0.035677408f, x * x, 0.7978845608f);
    float t;
    asm("tanh.approx.f32 %0, %1;" : "=f"(t) : "f"(z));
    const float hx = 0.5f * x;
    return fmaf(hx, t, hx);
}

// ---------------------------------------------------------------------------
// prep (merged): blocks 0..127 build g_base rows; blocks 128..191 build g_Wh;
// block 192 detects batch dtype (word [C-1] is 0 iff int64).
// ---------------------------------------------------------------------------
__global__ void __launch_bounds__(128) prep_kernel(
    const float* __restrict__ z_local, const float* __restrict__ z_meta,
    const float* __restrict__ W1, const float* __restrict__ b1,
    const int* __restrict__ batch_words, int C)
{
    if (blockIdx.x >= 128) {
        if (blockIdx.x == 192) {
            if (threadIdx.x == 0) g_is64 = (batch_words[C - 1] == 0) ? 1 : 0;
            return;
        }
        // g_Wh build: 64 blocks x 128 threads x 2 elements
        const int b = blockIdx.x - 128;
        #pragma unroll
        for (int h = 0; h < 2; ++h) {
            const int idx = (b * 128 + threadIdx.x) * 2 + h;   // 0..16383
            const int n = idx >> 7, k = idx & 127;
            g_Wh[n * 136 + k] = __float2half_rn(W1[k * Dv + n]);
        }
        return;
    }

    extern __shared__ float smem_f[];
    float* Wp  = smem_f;
    float* zsh = smem_f + 256 * Dv;
    const int tid = threadIdx.x;

    const float4* Wsrc = (const float4*)(W1 + Dv * Dv);
    float4* Wdst = (float4*)Wp;
    for (int i = tid; i < 256 * Dv / 4; i += 128) Wdst[i] = Wsrc[i];
    zsh[Dv + tid] = z_meta[tid];
    __syncthreads();

    const int b0 = blockIdx.x * 32;
    for (int g = 0; g < 32; ++g) {
        const int b = b0 + g;
        zsh[tid] = z_local[b * Dv + tid];
        __syncthreads();
        float a0 = 0.f, a1 = 0.f, a2 = 0.f, a3 = 0.f;
        #pragma unroll 4
        for (int k = 0; k < 256; k += 4) {
            a0 = fmaf(zsh[k + 0], Wp[(k + 0) * Dv + tid], a0);
            a1 = fmaf(zsh[k + 1], Wp[(k + 1) * Dv + tid], a1);
            a2 = fmaf(zsh[k + 2], Wp[(k + 2) * Dv + tid], a2);
            a3 = fmaf(zsh[k + 3], Wp[(k + 3) * Dv + tid], a3);
        }
        g_base[b * Dv + tid] = b1[tid] + ((a0 + a1) + (a2 + a3));
        __syncthreads();
    }
}

// ---------------------------------------------------------------------------
// Persistent main kernel, 512 threads (16 warps, warp tile 32M x 32N), fp16
// m16n8k16, fully pipelined: per-ks the mainloop of tile i carries the GELU
// epilogue of tile i-1 (base loads register-prefetched 2 ks ahead) and the
// fp32->fp16 convert of tile i+1 (own cp.async bytes -> no barrier). Batch
// indices for the NEXT epilogue load directly into pbidx at ks==6 (first
// point the old values are dead) — no separate bidx array.
// ---------------------------------------------------------------------------
__global__ void __launch_bounds__(512, 1) main_kernel(
    const float* __restrict__ nodes,
    const float* __restrict__ W2,
    const float* __restrict__ b2,
    const void*  __restrict__ batch,
    float* __restrict__ out, int C, int T)
{
    extern __shared__ float smem_f[];
    const uint32_t smem_base = smem_u32(smem_f);
    float* w2sh = smem_f + W2_OFF;
    float* red  = smem_f + RED_OFF;

    const int tid  = threadIdx.x;
    const int lane = tid & 31;
    const int warp = tid >> 5;
    const int wm   = warp >> 2;          // 0..3: rows wm*32
    const int wn   = warp & 3;           // 0..3: cols wn*32
    const int G    = gridDim.x;

    // ---- one-time Wh stage (34816 B = 2176 float4) ----
    {
        const float4* src = (const float4*)g_Wh;
        float4* dst = (float4*)(smem_f + WH_OFF);
        for (int idx = tid; idx < 2176; idx += 512) dst[idx] = src[idx];
        if (tid < 128) w2sh[tid] = W2[tid];
    }
    const float b2v  = b2[0];
    const int   is64 = g_is64;
    const int*       bt32 = (const int*)batch;
    const long long* bt64 = (const long long*)batch;

    // ---- ldmatrix lane addresses (fp16, pitch 272B) ----
    const int rowA = wm * 32 + (lane & 7) + ((lane >> 3) & 1) * 8;
    const uint32_t aA0 = smem_base + AH0_OFF * 4 + (uint32_t)rowA * 272
                       + ((lane >> 4) & 1) * 16;
    uint32_t bAdr[2];
    #pragma unroll
    for (int p = 0; p < 2; ++p) {
        const int nB = wn * 32 + p * 16 + (lane & 7) + ((lane >> 4) & 1) * 8;
        bAdr[p] = smem_base + WH_OFF * 4 + (uint32_t)nB * 272
                + ((lane >> 3) & 1) * 16;
    }

    auto issueA = [&](int t) {
        const int g0 = t * 128;
        int nr = C - g0; if (nr > 128) nr = 128;
        const char* src0 = (const char*)(nodes + (size_t)g0 * Dv);
        #pragma unroll
        for (int j = 0; j < 8; ++j) {
            const int e = j * 512 + tid;
            const int r = e >> 5, c = e & 31;
            if (r < nr) {
                const uint32_t dst = smem_base + (uint32_t)(r * 128 + c * 4) * 4;
                CP_ASYNC16(dst, src0 + (size_t)r * 512 + c * 16);
            }
        }
    };
    auto cvtChunk = [&](int wp, int j) {
        const int fi = j * 512 + tid;
        const int r = fi >> 5, c4 = fi & 31;
        const float4 v = ((const float4*)smem_f)[fi];
        uint2 hh;
        hh.x = pack_h2(v.x, v.y);
        hh.y = pack_h2(v.z, v.w);
        *(uint2*)((char*)smem_f + (AH0_OFF + wp * AH_STRIDE) * 4 + r * 272 + c4 * 8) = hh;
    };
    auto finishEpi = [&](int pgr0, float pp[4]) {
        #pragma unroll
        for (int tm = 0; tm < 2; ++tm)
            #pragma unroll
            for (int rh = 0; rh < 2; ++rh) {
                float partial = pp[tm * 2 + rh];
                partial += __shfl_xor_sync(0xFFFFFFFFu, partial, 1);
                partial += __shfl_xor_sync(0xFFFFFFFFu, partial, 2);
                const int row = wm * 32 + tm * 16 + rh * 8 + (lane >> 2);
                if ((lane & 3) == 0) red[row * 4 + wn] = partial;
            }
        __syncthreads();
        if (tid < 128) {
            const int g2 = pgr0 + tid;
            if (g2 < C) {
                const float4 rv = *(const float4*)(red + tid * 4);
                out[g2] = rv.x + rv.y + rv.z + rv.w + b2v;
            }
        }
    };

    float accN[8][4], accO[8][4];
    int   pbidx[2][2];
    int   pgr0 = 0;
    const int n0base = wn * 32 + (lane & 3) * 2;

    // load batch indices for tile origin gr0 directly into pbidx
    auto loadPbidx = [&](int gr0) {
        #pragma unroll
        for (int tm = 0; tm < 2; ++tm)
            #pragma unroll
            for (int rh = 0; rh < 2; ++rh) {
                const int gr = gr0 + wm * 32 + tm * 16 + rh * 8 + (lane >> 2);
                pbidx[tm][rh] = (gr < C) ? (is64 ? (int)bt64[gr] : bt32[gr]) : 0;
            }
    };
    // base-load register ring (distance-2 prefetch), per chunk: rows rh0/rh1
    auto ldBase = [&](int chunk, float2& o0, float2& o1) {
        const int tm = chunk >> 2, nt = chunk & 3;
        const int n0 = n0base + nt * 8;
        o0 = __ldg((const float2*)(g_base + pbidx[tm][0] * Dv + n0));
        o1 = __ldg((const float2*)(g_base + pbidx[tm][1] * Dv + n0));
    };

    int tile = blockIdx.x;
    if (tile >= T) return;

    // ---- prologue: stage + convert first tile serially; prefetch tile+G ----
    issueA(tile);
    CP_COMMIT();
    CP_WAIT0();
    #pragma unroll
    for (int j = 0; j < 8; ++j) cvtChunk(0, j);
    __syncthreads();
    if (tile + G < T) issueA(tile + G);
    CP_COMMIT();

    int ahp = 0;
    int doEpi = 0;

    for (; tile < T; tile += G) {
        #pragma unroll
        for (int n = 0; n < 8; ++n)
            #pragma unroll
            for (int i = 0; i < 4; ++i) accN[n][i] = 0.f;

        float pp[4] = {0.f, 0.f, 0.f, 0.f};
        const uint32_t aA = aA0 + (uint32_t)ahp * (AH_STRIDE * 4);
        const int wp = ahp ^ 1;
        const int cvtNext = (tile + G < T);

        // preload base values for epilogue chunks 0 and 1 (slots 0/1)
        float2 bvA0, bvA1, bvB0, bvB1;
        if (doEpi) { ldBase(0, bvA0, bvA1); ldBase(1, bvB0, bvB1); }

        #pragma unroll
        for (int ks = 0; ks < 8; ++ks) {
            uint32_t a0[4], a1[4], u0[4], u1[4];
            LDSM_X4(a0[0], a0[1], a0[2], a0[3], aA + ks * 32);
            LDSM_X4(a1[0], a1[1], a1[2], a1[3], aA + ks * 32 + 16 * 272);
            LDSM_X4(u0[0], u0[1], u0[2], u0[3], bAdr[0] + ks * 32);
            LDSM_X4(u1[0], u1[1], u1[2], u1[3], bAdr[1] + ks * 32);

            // epilogue chunk ks of tile i-1 (base values prefetched 2 iters ago)
            if (doEpi) {
                const int tm = ks >> 2, nt = ks & 3;
                const int n0 = n0base + nt * 8;
                const float2 w2v = *(const float2*)(w2sh + n0);
                const float2 bv0 = (ks & 1) ? bvB0 : bvA0;
                const float2 bv1 = (ks & 1) ? bvB1 : bvA1;
                const float x0 = accO[tm * 4 + nt][0] + bv0.x;
                const float x1 = accO[tm * 4 + nt][1] + bv0.y;
                const float x2 = accO[tm * 4 + nt][2] + bv1.x;
                const float x3 = accO[tm * 4 + nt][3] + bv1.y;
                pp[tm * 2 + 0] = fmaf(gelu_fast(x0), w2v.x, pp[tm * 2 + 0]);
                pp[tm * 2 + 0] = fmaf(gelu_fast(x1), w2v.y, pp[tm * 2 + 0]);
                pp[tm * 2 + 1] = fmaf(gelu_fast(x2), w2v.x, pp[tm * 2 + 1]);
                pp[tm * 2 + 1] = fmaf(gelu_fast(x3), w2v.y, pp[tm * 2 + 1]);
                // prefetch chunk ks+2 into the slot just consumed
                if (ks < 6) {
                    if (ks & 1) ldBase(ks + 2, bvB0, bvB1);
                    else        ldBase(ks + 2, bvA0, bvA1);
                }
            }

            // pbidx dead after ks==5's last ldBase -> load current tile's
            // indices here (ready well before next body's preloads)
            if (ks == 6) loadPbidx(tile * 128);

            // convert chunks of tile i+1 (own cp.async bytes -> no barrier)
            if (ks == 4) CP_WAIT0();
            if (ks >= 4 && cvtNext) {
                cvtChunk(wp, (ks - 4) * 2 + 0);
                cvtChunk(wp, (ks - 4) * 2 + 1);
            }

            MMA_F16(accN[0], a0, u0[0], u0[1]);
            MMA_F16(accN[1], a0, u0[2], u0[3]);
            MMA_F16(accN[2], a0, u1[0], u1[1]);
            MMA_F16(accN[3], a0, u1[2], u1[3]);
            MMA_F16(accN[4], a1, u0[0], u0[1]);
            MMA_F16(accN[5], a1, u0[2], u0[3]);
            MMA_F16(accN[6], a1, u1[0], u1[1]);
            MMA_F16(accN[7], a1, u1[2], u1[3]);
        }

        // S is consumed; prefetch tile i+2
        if (tile + 2 * G < T) issueA(tile + 2 * G);
        CP_COMMIT();

        if (doEpi) finishEpi(pgr0, pp);
        else       __syncthreads();      // publish AH[wp] for the next body

        #pragma unroll
        for (int n = 0; n < 8; ++n)
            #pragma unroll
            for (int i = 0; i < 4; ++i) accO[n][i] = accN[n][i];
        pgr0 = tile * 128;
        doEpi = 1;
        ahp ^= 1;
    }

    // ---- drain: standalone epilogue for the last tile ----
    {
        float pp[4] = {0.f, 0.f, 0.f, 0.f};
        #pragma unroll
        for (int ks = 0; ks < 8; ++ks) {
            const int tm = ks >> 2, nt = ks & 3;
            const int n0 = n0base + nt * 8;
            const float2 w2v = *(const float2*)(w2sh + n0);
            const float2 bv0 = __ldg((const float2*)(g_base + pbidx[tm][0] * Dv + n0));
            const float2 bv1 = __ldg((const float2*)(g_base + pbidx[tm][1] * Dv + n0));
            const float x0 = accO[tm * 4 + nt][0] + bv0.x;
            const float x1 = accO[tm * 4 + nt][1] + bv0.y;
            const float x2 = accO[tm * 4 + nt][2] + bv1.x;
            const float x3 = accO[tm * 4 + nt][3] + bv1.y;
            pp[tm * 2 + 0] = fmaf(gelu_fast(x0), w2v.x, pp[tm * 2 + 0]);
            pp[tm * 2 + 0] = fmaf(gelu_fast(x1), w2v.y, pp[tm * 2 + 0]);
            pp[tm * 2 + 1] = fmaf(gelu_fast(x2), w2v.x, pp[tm * 2 + 1]);
            pp[tm * 2 + 1] = fmaf(gelu_fast(x3), w2v.y, pp[tm * 2 + 1]);
        }
        __syncthreads();
        finishEpi(pgr0, pp);
    }
}

// ---------------------------------------------------------------------------
extern "C" void kernel_launch(void* const* d_in, const int* in_sizes, int n_in,
                              void* d_out, int out_size)
{
    const float* nodes   = (const float*)d_in[0];
    const float* z_local = (const float*)d_in[1];
    const float* z_meta  = (const float*)d_in[2];
    const float* W1      = (const float*)d_in[3];
    const float* b1      = (const float*)d_in[4];
    const float* W2      = (const float*)d_in[5];
    const float* b2      = (const float*)d_in[6];
    const void*  batch   = d_in[7];
    float* out = (float*)d_out;

    const int C = in_sizes[7];
    const int T = (C + 127) / 128;

    int dev = 0, nsm = 148;
    cudaGetDevice(&dev);
    cudaDeviceGetAttribute(&nsm, cudaDevAttrMultiProcessorCount, dev);

    const int PREP_SMEM = (256 * Dv + 256) * (int)sizeof(float);   // 132096
    const int MAIN_SMEM = SMEM_WORDS * (int)sizeof(float);         // 172544

    cudaFuncSetAttribute(prep_kernel, cudaFuncAttributeMaxDynamicSharedMemorySize, PREP_SMEM);
    cudaFuncSetAttribute(main_kernel, cudaFuncAttributeMaxDynamicSharedMemorySize, MAIN_SMEM);

    prep_kernel<<<193, 128, PREP_SMEM>>>(z_local, z_meta, W1, b1,
                                         (const int*)batch, C);

    main_kernel<<<nsm, 512, MAIN_SMEM>>>(nodes, W2, b2, batch, out, C, T);
}

// round 15
// speedup vs baseline: 1.8879x; 1.1821x over previous
#include <cuda_runtime.h>
#include <cuda_fp16.h>
#include <math.h>
#include <stdint.h>

#define Dv   128
#define Bv   4096

// SMEM word layout (main kernel)
#define S_OFF     0                       // fp32 stage: 128x128 (cp.async target)
#define AH0_OFF   16384                   // fp16 A tile 0: 128 x 136 halves (272B pitch)
#define AH_STRIDE 8704                    // words per AH buffer (34816 B)
#define AH1_OFF   (AH0_OFF + AH_STRIDE)   // 25088
#define WH_OFF    (AH1_OFF + AH_STRIDE)   // 33792
#define W2_OFF    (WH_OFF + AH_STRIDE)    // 42496
#define RED_OFF   (W2_OFF + 128)          // 42624
#define SMEM_WORDS (RED_OFF + 512)        // 43136 -> 172544 B

// prep SMEM layout (words)
#define PWP_OFF   0                       // W1 rows 128..383: 256x128 f32
#define PZM_OFF   32768                   // z_meta[128]
#define PZL_OFF   32896                   // z_local pair: 2x128
#define PCV_OFF   33152                   // cv[128] = b1 + z_meta·W1c
#define PREP_WORDS 33280                  // 133120 B

// Scratch globals
__device__ float g_base[Bv * Dv];                 // per-graph base rows (2 MB)
__device__ __align__(16) __half g_Wh[128 * 136];  // W1a^T fp16, pitch 136 halves
__device__ int   g_is64;

// ---------------- helpers ----------------
__device__ __forceinline__ uint32_t smem_u32(const void* p) {
    uint32_t a;
    asm("{ .reg .u64 t; cvta.to.shared.u64 t, %1; cvt.u32.u64 %0, t; }" : "=r"(a) : "l"(p));
    return a;
}
__device__ __forceinline__ uint32_t pack_h2(float lo, float hi) {
    uint32_t r;
    asm("cvt.rn.f16x2.f32 %0, %1, %2;" : "=r"(r) : "f"(hi), "f"(lo));
    return r;
}
#define CP_ASYNC16(dst, src) \
    asm volatile("cp.async.cg.shared.global [%0], [%1], 16;" :: "r"(dst), "l"(src) : "memory")
#define CP_COMMIT() asm volatile("cp.async.commit_group;" ::: "memory")
#define CP_WAIT0()  asm volatile("cp.async.wait_group 0;" ::: "memory")

#define LDSM_X4(r0, r1, r2, r3, addr)                                          \
    asm volatile("ldmatrix.sync.aligned.m8n8.x4.shared.b16 {%0,%1,%2,%3}, [%4];" \
        : "=r"(r0), "=r"(r1), "=r"(r2), "=r"(r3) : "r"(addr))

// mma.sync m16n8k16 fp16 -> fp32 accum
#define MMA_F16(c, a, b0_, b1_)                                                \
    asm volatile(                                                              \
        "mma.sync.aligned.m16n8k16.row.col.f32.f16.f16.f32 "                   \
        "{%0,%1,%2,%3}, {%4,%5,%6,%7}, {%8,%9}, {%0,%1,%2,%3};"                \
        : "+f"((c)[0]), "+f"((c)[1]), "+f"((c)[2]), "+f"((c)[3])               \
        : "r"((a)[0]), "r"((a)[1]), "r"((a)[2]), "r"((a)[3]),                  \
          "r"(b0_), "r"(b1_))

// gelu(x) = 0.5x(1+tanh(0.79788456x + 0.03567741x^3)) -- single MUFU tanh
__device__ __forceinline__ float gelu_fast(float x) {
    const float z = x * fmaf(0.035677408f, x * x, 0.7978845608f);
    float t;
    asm("tanh.approx.f32 %0, %1;" : "=f"(t) : "f"(z));
    const float hx = 0.5f * x;
    return fmaf(hx, t, hx);
}

// ---------------------------------------------------------------------------
// prep (merged): blocks 0..127 build g_base (32 graphs each, 2 concurrently
// across thread halves, k-loop halved via precomputed cv = b1 + z_meta·W1c);
// blocks 128..191 build g_Wh; block 192 detects batch dtype.
// ---------------------------------------------------------------------------
__global__ void __launch_bounds__(256) prep_kernel(
    const float* __restrict__ z_local, const float* __restrict__ z_meta,
    const float* __restrict__ W1, const float* __restrict__ b1,
    const int* __restrict__ batch_words, int C)
{
    if (blockIdx.x >= 128) {
        if (blockIdx.x == 192) {
            if (threadIdx.x == 0) g_is64 = (batch_words[C - 1] == 0) ? 1 : 0;
            return;
        }
        // g_Wh build: 64 blocks x 256 threads x 1 element
        const int idx = (blockIdx.x - 128) * 256 + threadIdx.x;   // 0..16383
        const int n = idx >> 7, k = idx & 127;
        g_Wh[n * 136 + k] = __float2half_rn(W1[k * Dv + n]);
        return;
    }

    extern __shared__ float smem_f[];
    float* Wp = smem_f + PWP_OFF;    // rows 0..127: W1b (z_local), 128..255: W1c (meta)
    float* zm = smem_f + PZM_OFF;
    float* zl = smem_f + PZL_OFF;
    float* cv = smem_f + PCV_OFF;

    const int tid  = threadIdx.x;
    const int t    = tid & 127;      // output dim
    const int gh   = tid >> 7;       // graph half (0/1)

    // stage W1 rows 128..383 (256x128 f32, 128 KB)
    {
        const float4* src = (const float4*)(W1 + Dv * Dv);
        float4* dst = (float4*)Wp;
        #pragma unroll
        for (int j = 0; j < 32; ++j) dst[j * 256 + tid] = src[j * 256 + tid];
    }
    if (tid < 128) zm[tid] = z_meta[tid];
    __syncthreads();

    // cv[t] = b1[t] + z_meta · W1c[:,t]   (once per block; warps 0..3)
    if (tid < 128) {
        float a0 = 0.f, a1 = 0.f, a2 = 0.f, a3 = 0.f;
        #pragma unroll 4
        for (int k = 0; k < 128; k += 4) {
            a0 = fmaf(zm[k + 0], Wp[(128 + k + 0) * Dv + t], a0);
            a1 = fmaf(zm[k + 1], Wp[(128 + k + 1) * Dv + t], a1);
            a2 = fmaf(zm[k + 2], Wp[(128 + k + 2) * Dv + t], a2);
            a3 = fmaf(zm[k + 3], Wp[(128 + k + 3) * Dv + t], a3);
        }
        cv[t] = b1[t] + ((a0 + a1) + (a2 + a3));
    }
    __syncthreads();

    // 16 pairs of graphs, 2 concurrently (thread half <-> graph)
    const int b0 = blockIdx.x * 32;
    for (int p = 0; p < 16; ++p) {
        const int b = b0 + p * 2 + gh;
        zl[gh * 128 + t] = z_local[b * Dv + t];
        __syncthreads();
        const float* zg = zl + gh * 128;
        float a0 = 0.f, a1 = 0.f, a2 = 0.f, a3 = 0.f;
        #pragma unroll 4
        for (int k = 0; k < 128; k += 4) {
            a0 = fmaf(zg[k + 0], Wp[(k + 0) * Dv + t], a0);
            a1 = fmaf(zg[k + 1], Wp[(k + 1) * Dv + t], a1);
            a2 = fmaf(zg[k + 2], Wp[(k + 2) * Dv + t], a2);
            a3 = fmaf(zg[k + 3], Wp[(k + 3) * Dv + t], a3);
        }
        g_base[b * Dv + t] = cv[t] + ((a0 + a1) + (a2 + a3));
        __syncthreads();
    }
}

// ---------------------------------------------------------------------------
// Persistent main kernel (unchanged from R14 best): 512 threads, fp16
// m16n8k16, cross-tile pipelined epilogue + staged cvt, base-load reg ring.
// ---------------------------------------------------------------------------
__global__ void __launch_bounds__(512, 1) main_kernel(
    const float* __restrict__ nodes,
    const float* __restrict__ W2,
    const float* __restrict__ b2,
    const void*  __restrict__ batch,
    float* __restrict__ out, int C, int T)
{
    extern __shared__ float smem_f[];
    const uint32_t smem_base = smem_u32(smem_f);
    float* w2sh = smem_f + W2_OFF;
    float* red  = smem_f + RED_OFF;

    const int tid  = threadIdx.x;
    const int lane = tid & 31;
    const int warp = tid >> 5;
    const int wm   = warp >> 2;          // 0..3: rows wm*32
    const int wn   = warp & 3;           // 0..3: cols wn*32
    const int G    = gridDim.x;

    // ---- one-time Wh stage (34816 B = 2176 float4) ----
    {
        const float4* src = (const float4*)g_Wh;
        float4* dst = (float4*)(smem_f + WH_OFF);
        for (int idx = tid; idx < 2176; idx += 512) dst[idx] = src[idx];
        if (tid < 128) w2sh[tid] = W2[tid];
    }
    const float b2v  = b2[0];
    const int   is64 = g_is64;
    const int*       bt32 = (const int*)batch;
    const long long* bt64 = (const long long*)batch;

    // ---- ldmatrix lane addresses (fp16, pitch 272B) ----
    const int rowA = wm * 32 + (lane & 7) + ((lane >> 3) & 1) * 8;
    const uint32_t aA0 = smem_base + AH0_OFF * 4 + (uint32_t)rowA * 272
                       + ((lane >> 4) & 1) * 16;
    uint32_t bAdr[2];
    #pragma unroll
    for (int p = 0; p < 2; ++p) {
        const int nB = wn * 32 + p * 16 + (lane & 7) + ((lane >> 4) & 1) * 8;
        bAdr[p] = smem_base + WH_OFF * 4 + (uint32_t)nB * 272
                + ((lane >> 3) & 1) * 16;
    }

    auto issueA = [&](int t) {
        const int g0 = t * 128;
        int nr = C - g0; if (nr > 128) nr = 128;
        const char* src0 = (const char*)(nodes + (size_t)g0 * Dv);
        #pragma unroll
        for (int j = 0; j < 8; ++j) {
            const int e = j * 512 + tid;
            const int r = e >> 5, c = e & 31;
            if (r < nr) {
                const uint32_t dst = smem_base + (uint32_t)(r * 128 + c * 4) * 4;
                CP_ASYNC16(dst, src0 + (size_t)r * 512 + c * 16);
            }
        }
    };
    auto cvtChunk = [&](int wp, int j) {
        const int fi = j * 512 + tid;
        const int r = fi >> 5, c4 = fi & 31;
        const float4 v = ((const float4*)smem_f)[fi];
        uint2 hh;
        hh.x = pack_h2(v.x, v.y);
        hh.y = pack_h2(v.z, v.w);
        *(uint2*)((char*)smem_f + (AH0_OFF + wp * AH_STRIDE) * 4 + r * 272 + c4 * 8) = hh;
    };
    auto finishEpi = [&](int pgr0, float pp[4]) {
        #pragma unroll
        for (int tm = 0; tm < 2; ++tm)
            #pragma unroll
            for (int rh = 0; rh < 2; ++rh) {
                float partial = pp[tm * 2 + rh];
                partial += __shfl_xor_sync(0xFFFFFFFFu, partial, 1);
                partial += __shfl_xor_sync(0xFFFFFFFFu, partial, 2);
                const int row = wm * 32 + tm * 16 + rh * 8 + (lane >> 2);
                if ((lane & 3) == 0) red[row * 4 + wn] = partial;
            }
        __syncthreads();
        if (tid < 128) {
            const int g2 = pgr0 + tid;
            if (g2 < C) {
                const float4 rv = *(const float4*)(red + tid * 4);
                out[g2] = rv.x + rv.y + rv.z + rv.w + b2v;
            }
        }
    };

    float accN[8][4], accO[8][4];
    int   pbidx[2][2];
    int   pgr0 = 0;
    const int n0base = wn * 32 + (lane & 3) * 2;

    auto loadPbidx = [&](int gr0) {
        #pragma unroll
        for (int tm = 0; tm < 2; ++tm)
            #pragma unroll
            for (int rh = 0; rh < 2; ++rh) {
                const int gr = gr0 + wm * 32 + tm * 16 + rh * 8 + (lane >> 2);
                pbidx[tm][rh] = (gr < C) ? (is64 ? (int)bt64[gr] : bt32[gr]) : 0;
            }
    };
    auto ldBase = [&](int chunk, float2& o0, float2& o1) {
        const int tm = chunk >> 2, nt = chunk & 3;
        const int n0 = n0base + nt * 8;
        o0 = __ldg((const float2*)(g_base + pbidx[tm][0] * Dv + n0));
        o1 = __ldg((const float2*)(g_base + pbidx[tm][1] * Dv + n0));
    };

    int tile = blockIdx.x;
    if (tile >= T) return;

    issueA(tile);
    CP_COMMIT();
    CP_WAIT0();
    #pragma unroll
    for (int j = 0; j < 8; ++j) cvtChunk(0, j);
    __syncthreads();
    if (tile + G < T) issueA(tile + G);
    CP_COMMIT();

    int ahp = 0;
    int doEpi = 0;

    for (; tile < T; tile += G) {
        #pragma unroll
        for (int n = 0; n < 8; ++n)
            #pragma unroll
            for (int i = 0; i < 4; ++i) accN[n][i] = 0.f;

        float pp[4] = {0.f, 0.f, 0.f, 0.f};
        const uint32_t aA = aA0 + (uint32_t)ahp * (AH_STRIDE * 4);
        const int wp = ahp ^ 1;
        const int cvtNext = (tile + G < T);

        float2 bvA0, bvA1, bvB0, bvB1;
        if (doEpi) { ldBase(0, bvA0, bvA1); ldBase(1, bvB0, bvB1); }

        #pragma unroll
        for (int ks = 0; ks < 8; ++ks) {
            uint32_t a0[4], a1[4], u0[4], u1[4];
            LDSM_X4(a0[0], a0[1], a0[2], a0[3], aA + ks * 32);
            LDSM_X4(a1[0], a1[1], a1[2], a1[3], aA + ks * 32 + 16 * 272);
            LDSM_X4(u0[0], u0[1], u0[2], u0[3], bAdr[0] + ks * 32);
            LDSM_X4(u1[0], u1[1], u1[2], u1[3], bAdr[1] + ks * 32);

            if (doEpi) {
                const int tm = ks >> 2, nt = ks & 3;
                const int n0 = n0base + nt * 8;
                const float2 w2v = *(const float2*)(w2sh + n0);
                const float2 bv0 = (ks & 1) ? bvB0 : bvA0;
                const float2 bv1 = (ks & 1) ? bvB1 : bvA1;
                const float x0 = accO[tm * 4 + nt][0] + bv0.x;
                const float x1 = accO[tm * 4 + nt][1] + bv0.y;
                const float x2 = accO[tm * 4 + nt][2] + bv1.x;
                const float x3 = accO[tm * 4 + nt][3] + bv1.y;
                pp[tm * 2 + 0] = fmaf(gelu_fast(x0), w2v.x, pp[tm * 2 + 0]);
                pp[tm * 2 + 0] = fmaf(gelu_fast(x1), w2v.y, pp[tm * 2 + 0]);
                pp[tm * 2 + 1] = fmaf(gelu_fast(x2), w2v.x, pp[tm * 2 + 1]);
                pp[tm * 2 + 1] = fmaf(gelu_fast(x3), w2v.y, pp[tm * 2 + 1]);
                if (ks < 6) {
                    if (ks & 1) ldBase(ks + 2, bvB0, bvB1);
                    else        ldBase(ks + 2, bvA0, bvA1);
                }
            }

            if (ks == 6) loadPbidx(tile * 128);

            if (ks == 4) CP_WAIT0();
            if (ks >= 4 && cvtNext) {
                cvtChunk(wp, (ks - 4) * 2 + 0);
                cvtChunk(wp, (ks - 4) * 2 + 1);
            }

            MMA_F16(accN[0], a0, u0[0], u0[1]);
            MMA_F16(accN[1], a0, u0[2], u0[3]);
            MMA_F16(accN[2], a0, u1[0], u1[1]);
            MMA_F16(accN[3], a0, u1[2], u1[3]);
            MMA_F16(accN[4], a1, u0[0], u0[1]);
            MMA_F16(accN[5], a1, u0[2], u0[3]);
            MMA_F16(accN[6], a1, u1[0], u1[1]);
            MMA_F16(accN[7], a1, u1[2], u1[3]);
        }

        if (tile + 2 * G < T) issueA(tile + 2 * G);
        CP_COMMIT();

        if (doEpi) finishEpi(pgr0, pp);
        else       __syncthreads();

        #pragma unroll
        for (int n = 0; n < 8; ++n)
            #pragma unroll
            for (int i = 0; i < 4; ++i) accO[n][i] = accN[n][i];
        pgr0 = tile * 128;
        doEpi = 1;
        ahp ^= 1;
    }

    // ---- drain: standalone epilogue for the last tile ----
    {
        float pp[4] = {0.f, 0.f, 0.f, 0.f};
        #pragma unroll
        for (int ks = 0; ks < 8; ++ks) {
            const int tm = ks >> 2, nt = ks & 3;
            const int n0 = n0base + nt * 8;
            const float2 w2v = *(const float2*)(w2sh + n0);
            const float2 bv0 = __ldg((const float2*)(g_base + pbidx[tm][0] * Dv + n0));
            const float2 bv1 = __ldg((const float2*)(g_base + pbidx[tm][1] * Dv + n0));
            const float x0 = accO[tm * 4 + nt][0] + bv0.x;
            const float x1 = accO[tm * 4 + nt][1] + bv0.y;
            const float x2 = accO[tm * 4 + nt][2] + bv1.x;
            const float x3 = accO[tm * 4 + nt][3] + bv1.y;
            pp[tm * 2 + 0] = fmaf(gelu_fast(x0), w2v.x, pp[tm * 2 + 0]);
            pp[tm * 2 + 0] = fmaf(gelu_fast(x1), w2v.y, pp[tm * 2 + 0]);
            pp[tm * 2 + 1] = fmaf(gelu_fast(x2), w2v.x, pp[tm * 2 + 1]);
            pp[tm * 2 + 1] = fmaf(gelu_fast(x3), w2v.y, pp[tm * 2 + 1]);
        }
        __syncthreads();
        finishEpi(pgr0, pp);
    }
}

// ---------------------------------------------------------------------------
extern "C" void kernel_launch(void* const* d_in, const int* in_sizes, int n_in,
                              void* d_out, int out_size)
{
    const float* nodes   = (const float*)d_in[0];
    const float* z_local = (const float*)d_in[1];
    const float* z_meta  = (const float*)d_in[2];
    const float* W1      = (const float*)d_in[3];
    const float* b1      = (const float*)d_in[4];
    const float* W2      = (const float*)d_in[5];
    const float* b2      = (const float*)d_in[6];
    const void*  batch   = d_in[7];
    float* out = (float*)d_out;

    const int C = in_sizes[7];
    const int T = (C + 127) / 128;

    int dev = 0, nsm = 148;
    cudaGetDevice(&dev);
    cudaDeviceGetAttribute(&nsm, cudaDevAttrMultiProcessorCount, dev);

    const int PREP_SMEM = PREP_WORDS * (int)sizeof(float);   // 133120
    const int MAIN_SMEM = SMEM_WORDS * (int)sizeof(float);   // 172544

    cudaFuncSetAttribute(prep_kernel, cudaFuncAttributeMaxDynamicSharedMemorySize, PREP_SMEM);
    cudaFuncSetAttribute(main_kernel, cudaFuncAttributeMaxDynamicSharedMemorySize, MAIN_SMEM);

    prep_kernel<<<193, 256, PREP_SMEM>>>(z_local, z_meta, W1, b1,
                                         (const int*)batch, C);

    main_kernel<<<nsm, 512, MAIN_SMEM>>>(nodes, W2, b2, batch, out, C, T);
}